// round 13
// baseline (speedup 1.0000x reference)
#include <cuda_runtime.h>
#include <cuda_fp16.h>

// ---------------- problem constants (fixed by the dataset) ----------------
#define NN   100000     // nodes
#define NE   1600000    // edges
#define NGR  256        // graphs
#define NF   64         // node feat
#define NF2  128        // 2*NF
#define EFB  40         // rbf bins
#define NL   3          // layers
#define NAT  95         // atom types
#define NAF  200        // atom feat
#define TAB  8192       // e_lin nearest-lookup intervals over [0,8]
#define TROWS (TAB + 1)
#define BN_EPS 1e-5f
#define NCHUNK ((NN + 1023) / 1024)   // 98 scan chunks

// Channel-permuted storage for hs/hd/tab/AB:
//   storage pos p = 8g+r:  r<4 -> orig gate channel 4g+r ; r>=4 -> orig value 64+4g+(r-4)
__device__ __forceinline__ int perm_c(int n) {       // orig -> storage
    return (n < 64) ? (((n >> 2) << 3) | (n & 3))
                    : ((((n & 63) >> 2) << 3) | 4 | (n & 3));
}
__device__ __forceinline__ int orig_c(int p) {       // storage -> orig
    int g = p >> 3, r = p & 7;
    return (r < 4) ? ((g << 2) + r) : (64 + (g << 2) + (r - 4));
}

// ---------------- persistent device scratch (no runtime allocation) -------
__device__ float  g_x   [NN * NF];          // x ping buffer
__device__ float  g_x2  [NN * NF];          // x pong buffer
__device__ __half g_hs  [NN * NF2];         // permuted cols
__device__ __half g_hd  [NN * NF2];         // permuted cols
__device__ float  g_h   [NN * NF];
__device__ __half g_tab [NL * TROWS * NF2]; // all 3 layers, permuted cols
__device__ float  g_emb [NAT * NF];
__device__ int    g_rowptr[NN + 1];
__device__ int    g_cursor[NN];
__device__ int    g_blk [128];
__device__ int    g_csr [NE];               // packed: src | (bin<<17)
__device__ float  g_esum[NF2];
__device__ float  g_esq [NF2];
__device__ float  g_AB  [2 * NF2];
__device__ float  g_nsum[NF];
__device__ float  g_nsq [NF];
__device__ float  g_pool[NGR * NF];
__device__ float  g_cnt [NGR];

// ---------------- helpers -------------------------------------------------
__device__ __forceinline__ float tanh_f(float x) {
    float r; asm("tanh.approx.f32 %0, %1;" : "=f"(r) : "f"(x)); return r;
}
__device__ __forceinline__ float ex2_f(float x) {
    float r; asm("ex2.approx.f32 %0, %1;" : "=f"(r) : "f"(x)); return r;
}
__device__ __forceinline__ float lg2_f(float x) {
    float r; asm("lg2.approx.f32 %0, %1;" : "=f"(r) : "f"(x)); return r;
}
__device__ __forceinline__ float sig_f(float x) {    // 1 MUFU
    return fmaf(0.5f, tanh_f(0.5f * x), 0.5f);
}
__device__ __forceinline__ float sp_f(float x) {     // 2 MUFU, overflow-safe
    float e = ex2_f(-fabsf(x) * 1.4426950408889634f);
    return fmaxf(x, 0.0f) + 0.6931471805599453f * lg2_f(1.0f + e);
}
__device__ __forceinline__ void mma16816(float c[4],
                                         unsigned a0, unsigned a1, unsigned a2, unsigned a3,
                                         unsigned b0, unsigned b1) {
    asm volatile(
        "mma.sync.aligned.m16n8k16.row.col.f32.f16.f16.f32 "
        "{%0,%1,%2,%3}, {%4,%5,%6,%7}, {%8,%9}, {%0,%1,%2,%3};\n"
        : "+f"(c[0]), "+f"(c[1]), "+f"(c[2]), "+f"(c[3])
        : "r"(a0), "r"(a1), "r"(a2), "r"(a3), "r"(b0), "r"(b1));
}

// --------------- 0a: fold atom featurizer + embedding into [95,64] --------
__global__ void k_emb(const float* __restrict__ at, const float* __restrict__ W,
                      const float* __restrict__ b) {
    int a = blockIdx.x, c = threadIdx.x;
    float acc = b[c];
    for (int k = 0; k < NAF; ++k)
        acc += at[a * NAF + k] * W[k * NF + c];
    g_emb[a * NF + c] = acc;
}

// --------------- 0b: x[n] = emb[type[n]]  (+ cursor & edge-stat zeroing) --
__global__ void k_gather_x(const int* __restrict__ types) {
    int i0 = blockIdx.x * blockDim.x + threadIdx.x;
    if (i0 < NF2) { g_esum[i0] = 0.0f; g_esq[i0] = 0.0f; }
    for (int i = i0; i < NN; i += gridDim.x * blockDim.x) g_cursor[i] = 0;
    const int total = NN * (NF / 4);
    for (int i = i0; i < total; i += gridDim.x * blockDim.x) {
        int n = i >> 4, j = i & 15;
        int t = __ldg(&types[n]);
        reinterpret_cast<float4*>(g_x)[i] =
            reinterpret_cast<const float4*>(g_emb)[t * (NF / 4) + j];
    }
}

// --------------- CSR build (one-time) -------------------------------------
__global__ void k_csr_hist(const int* __restrict__ dst) {
    int e = blockIdx.x * blockDim.x + threadIdx.x;
    for (; e < NE; e += gridDim.x * blockDim.x)
        atomicAdd(&g_cursor[__ldg(&dst[e])], 1);
}
__global__ void k_scan1() {
    __shared__ int wsum[32];
    const int tid = threadIdx.x;
    const int i = blockIdx.x * 1024 + tid;
    int v = (i < NN) ? g_cursor[i] : 0;
    int x = v;
#pragma unroll
    for (int off = 1; off < 32; off <<= 1) {
        int y = __shfl_up_sync(0xffffffffu, x, off);
        if ((tid & 31) >= off) x += y;
    }
    if ((tid & 31) == 31) wsum[tid >> 5] = x;
    __syncthreads();
    if (tid < 32) {
        int w = wsum[tid];
#pragma unroll
        for (int off = 1; off < 32; off <<= 1) {
            int y = __shfl_up_sync(0xffffffffu, w, off);
            if (tid >= off) w += y;
        }
        wsum[tid] = w;
    }
    __syncthreads();
    int warpoff = (tid >= 32) ? wsum[(tid >> 5) - 1] : 0;
    int excl = warpoff + x - v;
    if (i < NN) g_rowptr[i] = excl;
    if (tid == 1023) g_blk[blockIdx.x] = warpoff + x;
}
__global__ void k_scan2() {
    __shared__ int s[128];
    const int tid = threadIdx.x;
    int v = (tid < NCHUNK) ? g_blk[tid] : 0;
    s[tid] = v;
    __syncthreads();
    for (int off = 1; off < 128; off <<= 1) {
        int t = (tid >= off) ? s[tid - off] : 0;
        __syncthreads();
        s[tid] += t;
        __syncthreads();
    }
    if (tid < NCHUNK) g_blk[tid] = s[tid] - v;
}
__global__ void k_scan3() {
    int i = blockIdx.x * blockDim.x + threadIdx.x;
    for (; i < NN; i += gridDim.x * blockDim.x) {
        int r = g_rowptr[i] + g_blk[i >> 10];
        g_rowptr[i] = r;
        g_cursor[i] = r;
    }
    if (blockIdx.x == 0 && threadIdx.x == 0) g_rowptr[NN] = NE;
}
__global__ void k_csr_scatter(const int* __restrict__ src, const int* __restrict__ dst,
                              const float* __restrict__ dist) {
    int e = blockIdx.x * blockDim.x + threadIdx.x;
    for (; e < NE; e += gridDim.x * blockDim.x) {
        int d = __ldg(&dst[e]);
        int pos = atomicAdd(&g_cursor[d], 1);
        int bin = min(__float2int_rn(__ldg(&dist[e]) * (TAB / 8.0f)), TAB);
        g_csr[pos] = __ldg(&src[e]) | (bin << 17);
    }
}

// --------------- all-layer e_lin tables (fp16, permuted) ------------------
__global__ void k_tab_all(const float* __restrict__ We, const float* __restrict__ be) {
    __shared__ float phi[4][EFB];
    const int p  = threadIdx.x;
    const int oc = orig_c(p);
    const int r0 = blockIdx.x * 4;
    if (p < EFB) {
        float ctr = p * (8.0f / 39.0f);
#pragma unroll
        for (int r = 0; r < 4; ++r) {
            int grow = r0 + r;
            int rr = grow % TROWS;
            float x = rr * (8.0f / TAB) - ctr;
            phi[r][p] = expf(-4.875f * x * x);
        }
    }
    __syncthreads();
#pragma unroll
    for (int r = 0; r < 4; ++r) {
        int grow = r0 + r;
        if (grow >= NL * TROWS) break;
        int l = grow / TROWS;
        const float* W = We + l * EFB * NF2;
        float acc = be[l * NF2 + oc];
#pragma unroll
        for (int k = 0; k < EFB; ++k)
            acc += phi[r][k] * W[k * NF2 + oc];
        g_tab[grow * NF2 + p] = __float2half_rn(acc);
    }
}

// --------------- node GEMM via tensor cores; optional fused x-update ------
// xsel: 0 -> xin=g_x, xout=g_x2 ; 1 -> xin=g_x2, xout=g_x  (all in-kernel)
__global__ __launch_bounds__(256) void k_node_gemm(
    const float* __restrict__ Wsrc, const float* __restrict__ bsrc,
    const float* __restrict__ Wdst, const float* __restrict__ bdst, int l,
    int xsel, int fuse,
    const float* __restrict__ gb, const float* __restrict__ bb) {
    const float* xin  = xsel ? g_x2 : g_x;
    float*       xout = xsel ? g_x  : g_x2;
    const float* W = (blockIdx.y == 0 ? Wsrc : Wdst) + l * NF * NF2;
    const float* b = (blockIdx.y == 0 ? bsrc : bdst) + l * NF2;
    __half*      H = (blockIdx.y == 0 ? g_hs : g_hd);

    __shared__ __half xs[128 * 72];
    __shared__ __half wt[128 * 72];
    __shared__ float sA[NF], sB[NF];

    const int tid = threadIdx.x;
    const int nb = blockIdx.x * 128;

    if (fuse && tid < NF) {                             // BN consts of layer l-1
        float mean = g_nsum[tid] * (1.0f / NN);
        float var  = fmaxf(g_nsq[tid] * (1.0f / NN) - mean * mean, 0.0f);
        float A = gb[(l - 1) * NF + tid] * rsqrtf(var + BN_EPS);
        sA[tid] = A;
        sB[tid] = bb[(l - 1) * NF + tid] - mean * A;
    }

#pragma unroll
    for (int i = 0; i < 32; ++i) {
        int idx = i * 256 + tid;
        int k = idx >> 7, n = idx & 127;
        wt[n * 72 + k] = __float2half_rn(W[idx]);
    }
    __syncthreads();                                    // sA/sB + wt ready
#pragma unroll
    for (int i = 0; i < 16; ++i) {
        int idx = i * 256 + tid;
        int row = idx >> 5, cp = idx & 31;
        int gr = nb + row;
        int grc = (gr >= NN) ? NN - 1 : gr;
        float2 v = *reinterpret_cast<const float2*>(xin + grc * NF + cp * 2);
        if (fuse) {
            float2 h = *reinterpret_cast<const float2*>(g_h + grc * NF + cp * 2);
            int c0 = cp * 2;
            v.x = sp_f(v.x + sA[c0] * h.x + sB[c0]);
            v.y = sp_f(v.y + sA[c0 + 1] * h.y + sB[c0 + 1]);
            if (blockIdx.y == 0 && gr < NN)
                *reinterpret_cast<float2*>(xout + gr * NF + cp * 2) = v;
        }
        *reinterpret_cast<__half2*>(&xs[row * 72 + cp * 2]) = __floats2half2_rn(v.x, v.y);
    }
    __syncthreads();

    const int w = tid >> 5, lane = tid & 31;
    const int m0 = (w & 3) * 32, n0 = (w >> 2) * 64;
    const int lr = lane >> 2, lc = (lane & 3) * 2;

    float c[2][8][4];
#pragma unroll
    for (int mt = 0; mt < 2; ++mt)
#pragma unroll
        for (int nt = 0; nt < 8; ++nt)
            c[mt][nt][0] = c[mt][nt][1] = c[mt][nt][2] = c[mt][nt][3] = 0.0f;

#pragma unroll
    for (int ks = 0; ks < 4; ++ks) {
        const int kk = ks * 16 + lc;
        unsigned bf[8][2];
#pragma unroll
        for (int nt = 0; nt < 8; ++nt) {
            int n = n0 + nt * 8 + lr;
            bf[nt][0] = *reinterpret_cast<unsigned*>(&wt[n * 72 + kk]);
            bf[nt][1] = *reinterpret_cast<unsigned*>(&wt[n * 72 + kk + 8]);
        }
#pragma unroll
        for (int mt = 0; mt < 2; ++mt) {
            int r = m0 + mt * 16 + lr;
            unsigned a0 = *reinterpret_cast<unsigned*>(&xs[r * 72 + kk]);
            unsigned a1 = *reinterpret_cast<unsigned*>(&xs[(r + 8) * 72 + kk]);
            unsigned a2 = *reinterpret_cast<unsigned*>(&xs[r * 72 + kk + 8]);
            unsigned a3 = *reinterpret_cast<unsigned*>(&xs[(r + 8) * 72 + kk + 8]);
#pragma unroll
            for (int nt = 0; nt < 8; ++nt)
                mma16816(c[mt][nt], a0, a1, a2, a3, bf[nt][0], bf[nt][1]);
        }
    }

#pragma unroll
    for (int nt = 0; nt < 8; ++nt) {
        int n = n0 + nt * 8 + lc;
        int pos = perm_c(n);
        float2 bv = *reinterpret_cast<const float2*>(b + n);
#pragma unroll
        for (int mt = 0; mt < 2; ++mt) {
            int r = nb + m0 + mt * 16 + lr;
            __half2 h01 = __floats2half2_rn(c[mt][nt][0] + bv.x, c[mt][nt][1] + bv.y);
            __half2 h23 = __floats2half2_rn(c[mt][nt][2] + bv.x, c[mt][nt][3] + bv.y);
            if (r < NN)     *reinterpret_cast<__half2*>(H + r * NF2 + pos) = h01;
            if (r + 8 < NN) *reinterpret_cast<__half2*>(H + (r + 8) * NF2 + pos) = h23;
        }
    }
}

// --------------- pass A: CSR stats, 4-edge unrolled (MLP=8) ---------------
__global__ __launch_bounds__(256) void k_edge_stats(int l) {
    const int lane = threadIdx.x & 31;
    const int half = lane >> 4;
    const int t    = lane & 15;
    int       wid  = (blockIdx.x * blockDim.x + threadIdx.x) >> 5;
    const int nw   = (gridDim.x * blockDim.x) >> 5;
    const uint4* tabp = reinterpret_cast<const uint4*>(g_tab) + l * TROWS * 16;
    float2 s2[4], q2[4];
#pragma unroll
    for (int j = 0; j < 4; ++j) { s2[j] = make_float2(0, 0); q2[j] = make_float2(0, 0); }

    for (int n = wid; n < NN; n += nw) {
        const int e0 = __ldg(&g_rowptr[n]);
        const int e1 = __ldg(&g_rowptr[n + 1]);
        if (e0 == e1) continue;
        uint4 ub = reinterpret_cast<const uint4*>(g_hd)[n * 16 + t];
        float2 vb[4];
#pragma unroll
        for (int j = 0; j < 4; ++j)
            vb[j] = __half22float2(reinterpret_cast<const __half2*>(&ub)[j]);

        for (int es = e0; es < e1; es += 32) {
            int pk = (es + lane < e1) ? g_csr[es + lane] : 0;
            const int cnt = min(32, e1 - es);
            for (int j = 0; j < cnt; j += 8) {
                int  pks[4]; bool act[4];
                uint4 ua[4], ut[4];
#pragma unroll
                for (int u = 0; u < 4; ++u) {
                    int jj = j + 2 * u + half;
                    act[u] = (jj < cnt);
                    pks[u] = __shfl_sync(0xffffffffu, pk, jj & 31);
                }
#pragma unroll
                for (int u = 0; u < 4; ++u) {
                    if (act[u]) {
                        ua[u] = reinterpret_cast<const uint4*>(g_hs)[(pks[u] & 0x1FFFF) * 16 + t];
                        ut[u] = tabp[(((unsigned)pks[u]) >> 17) * 16 + t];
                    }
                }
#pragma unroll
                for (int u = 0; u < 4; ++u) {
                    if (act[u]) {
#pragma unroll
                        for (int q = 0; q < 4; ++q) {
                            float2 va = __half22float2(reinterpret_cast<const __half2*>(&ua[u])[q]);
                            float2 vt = __half22float2(reinterpret_cast<const __half2*>(&ut[u])[q]);
                            float mx = va.x + vb[q].x + vt.x;
                            float my = va.y + vb[q].y + vt.y;
                            s2[q].x += mx;      s2[q].y += my;
                            q2[q].x += mx * mx; q2[q].y += my * my;
                        }
                    }
                }
            }
        }
    }
    __shared__ float ss[NF2], sq[NF2];
    if (threadIdx.x < NF2) { ss[threadIdx.x] = 0.0f; sq[threadIdx.x] = 0.0f; }
    __syncthreads();
#pragma unroll
    for (int j = 0; j < 4; ++j) {
        atomicAdd(&ss[t * 8 + 2 * j],     s2[j].x);
        atomicAdd(&ss[t * 8 + 2 * j + 1], s2[j].y);
        atomicAdd(&sq[t * 8 + 2 * j],     q2[j].x);
        atomicAdd(&sq[t * 8 + 2 * j + 1], q2[j].y);
    }
    __syncthreads();
    if (threadIdx.x < NF2) {
        atomicAdd(&g_esum[threadIdx.x], ss[threadIdx.x]);
        atomicAdd(&g_esq [threadIdx.x], sq[threadIdx.x]);
    }
}

// --------------- fold BN into y = A*m + B; zero accums for next stage -----
__global__ void k_finalize(const float* __restrict__ gm, const float* __restrict__ bm,
                           int l, int zero_pool) {
    int p = threadIdx.x;                                // 128
    int oc = orig_c(p);
    float mean = g_esum[p] * (1.0f / NE);
    float var  = fmaxf(g_esq[p] * (1.0f / NE) - mean * mean, 0.0f);
    float A = gm[l * NF2 + oc] * rsqrtf(var + BN_EPS);
    g_AB[p]       = A;
    g_AB[NF2 + p] = bm[l * NF2 + oc] - mean * A;
    g_esum[p] = 0.0f;                                   // ready for next layer
    g_esq [p] = 0.0f;
    if (p < NF) { g_nsum[p] = 0.0f; g_nsq[p] = 0.0f; }
    if (zero_pool) {
        for (int i = blockIdx.x * 128 + p; i < NGR * NF + NGR; i += gridDim.x * 128) {
            if (i < NGR * NF) g_pool[i] = 0.0f;
            else g_cnt[i - NGR * NF] = 0.0f;
        }
    }
}

// --------------- pass B: CSR gather, dense gate, 4-edge unrolled ----------
__global__ __launch_bounds__(256) void k_edge_apply(int l) {
    const int lane = threadIdx.x & 31;
    const int half = lane >> 4;
    const int t    = lane & 15;
    int       wid  = (blockIdx.x * blockDim.x + threadIdx.x) >> 5;
    const int nw   = (gridDim.x * blockDim.x) >> 5;
    const uint4* tabp = reinterpret_cast<const uint4*>(g_tab) + l * TROWS * 16;

    const float4 A0 = reinterpret_cast<const float4*>(g_AB)[t * 2];
    const float4 A1 = reinterpret_cast<const float4*>(g_AB)[t * 2 + 1];
    const float4 B0 = reinterpret_cast<const float4*>(g_AB + NF2)[t * 2];
    const float4 B1 = reinterpret_cast<const float4*>(g_AB + NF2)[t * 2 + 1];

    float hsum[4], hsq[4];
#pragma unroll
    for (int i = 0; i < 4; ++i) { hsum[i] = 0.0f; hsq[i] = 0.0f; }

    for (int n = wid; n < NN; n += nw) {
        const int e0 = __ldg(&g_rowptr[n]);
        const int e1 = __ldg(&g_rowptr[n + 1]);

        float hacc[4];
#pragma unroll
        for (int i = 0; i < 4; ++i) hacc[i] = 0.0f;

        if (e0 != e1) {
            uint4 ub = reinterpret_cast<const uint4*>(g_hd)[n * 16 + t];
            float2 vb[4];
#pragma unroll
            for (int j = 0; j < 4; ++j)
                vb[j] = __half22float2(reinterpret_cast<const __half2*>(&ub)[j]);

            for (int es = e0; es < e1; es += 32) {
                int pk = (es + lane < e1) ? g_csr[es + lane] : 0;
                const int cnt = min(32, e1 - es);
                for (int j = 0; j < cnt; j += 8) {
                    int  pks[4]; bool act[4];
                    uint4 ua[4], ut[4];
#pragma unroll
                    for (int u = 0; u < 4; ++u) {
                        int jj = j + 2 * u + half;
                        act[u] = (jj < cnt);
                        pks[u] = __shfl_sync(0xffffffffu, pk, jj & 31);
                    }
#pragma unroll
                    for (int u = 0; u < 4; ++u) {
                        if (act[u]) {
                            ua[u] = reinterpret_cast<const uint4*>(g_hs)[(pks[u] & 0x1FFFF) * 16 + t];
                            ut[u] = tabp[(((unsigned)pks[u]) >> 17) * 16 + t];
                        }
                    }
#pragma unroll
                    for (int u = 0; u < 4; ++u) {
                        if (!act[u]) continue;
                        float m[8];
#pragma unroll
                        for (int q = 0; q < 4; ++q) {
                            float2 va = __half22float2(reinterpret_cast<const __half2*>(&ua[u])[q]);
                            float2 vt = __half22float2(reinterpret_cast<const __half2*>(&ut[u])[q]);
                            m[2 * q]     = va.x + vb[q].x + vt.x;
                            m[2 * q + 1] = va.y + vb[q].y + vt.y;
                        }
                        float yg0 = A0.x * m[0] + B0.x;
                        float yg1 = A0.y * m[1] + B0.y;
                        float yg2 = A0.z * m[2] + B0.z;
                        float yg3 = A0.w * m[3] + B0.w;
                        float yv0 = A1.x * m[4] + B1.x;
                        float yv1 = A1.y * m[5] + B1.y;
                        float yv2 = A1.z * m[6] + B1.z;
                        float yv3 = A1.w * m[7] + B1.w;
                        hacc[0] += sig_f(yg0) * sp_f(yv0);
                        hacc[1] += sig_f(yg1) * sp_f(yv1);
                        hacc[2] += sig_f(yg2) * sp_f(yv2);
                        hacc[3] += sig_f(yg3) * sp_f(yv3);
                    }
                }
            }
        }
        float tot[4];
#pragma unroll
        for (int i = 0; i < 4; ++i) {
            float o = __shfl_down_sync(0xffffffffu, hacc[i], 16);
            tot[i] = hacc[i] + o;
        }
        if (lane < 16) {
            *reinterpret_cast<float4*>(g_h + n * NF + lane * 4) =
                make_float4(tot[0], tot[1], tot[2], tot[3]);
#pragma unroll
            for (int i = 0; i < 4; ++i) {
                hsum[i] += tot[i];
                hsq[i]  += tot[i] * tot[i];
            }
        }
    }
    __shared__ float ss[NF], sq[NF];
    if (threadIdx.x < NF) { ss[threadIdx.x] = 0.0f; sq[threadIdx.x] = 0.0f; }
    __syncthreads();
    if (lane < 16) {
#pragma unroll
        for (int i = 0; i < 4; ++i) {
            atomicAdd(&ss[t * 4 + i], hsum[i]);
            atomicAdd(&sq[t * 4 + i], hsq[i]);
        }
    }
    __syncthreads();
    if (threadIdx.x < NF) {
        atomicAdd(&g_nsum[threadIdx.x], ss[threadIdx.x]);
        atomicAdd(&g_nsq [threadIdx.x], sq[threadIdx.x]);
    }
}

// --------------- pool: fused final x-update + segmented sum (gid sorted) --
// final x (layer NL-1 input) lives in g_x for NL=3; update applied inline
__global__ __launch_bounds__(256) void k_pool(const int* __restrict__ gid,
                                              const float* __restrict__ gb,
                                              const float* __restrict__ bb, int l) {
    __shared__ float sA[NF], sB[NF];
    const int tid = threadIdx.x;
    if (tid < NF) {
        float mean = g_nsum[tid] * (1.0f / NN);
        float var  = fmaxf(g_nsq[tid] * (1.0f / NN) - mean * mean, 0.0f);
        float A = gb[l * NF + tid] * rsqrtf(var + BN_EPS);
        sA[tid] = A;
        sB[tid] = bb[l * NF + tid] - mean * A;
    }
    __syncthreads();

    const int lane = tid & 31;
    const int wid  = (blockIdx.x * blockDim.x + tid) >> 5;
    const int nwarp = (gridDim.x * blockDim.x) >> 5;
    const int per = (NN + nwarp - 1) / nwarp;
    const int n0 = wid * per;
    const int n1 = min(NN, n0 + per);
    if (n0 >= n1) return;

    const int c0 = (lane & 15) * 4;
    float4 acc = make_float4(0, 0, 0, 0);
    int cnt = 0, gcur = -1;

    for (int n = n0; n < n1; ++n) {
        int g = __ldg(&gid[n]);
        if (g != gcur) {
            if (cnt > 0 && lane < 16) {
                atomicAdd(reinterpret_cast<float4*>(g_pool + gcur * NF + c0), acc);
                if (lane == 0) atomicAdd(&g_cnt[gcur], (float)cnt);
            }
            acc = make_float4(0, 0, 0, 0);
            cnt = 0;
            gcur = g;
        }
        if (lane < 16) {
            float4 xv = *reinterpret_cast<const float4*>(g_x + n * NF + c0);
            float4 hv = *reinterpret_cast<const float4*>(g_h + n * NF + c0);
            acc.x += sp_f(xv.x + sA[c0]     * hv.x + sB[c0]);
            acc.y += sp_f(xv.y + sA[c0 + 1] * hv.y + sB[c0 + 1]);
            acc.z += sp_f(xv.z + sA[c0 + 2] * hv.z + sB[c0 + 2]);
            acc.w += sp_f(xv.w + sA[c0 + 3] * hv.w + sB[c0 + 3]);
        }
        ++cnt;
    }
    if (cnt > 0 && lane < 16) {
        atomicAdd(reinterpret_cast<float4*>(g_pool + gcur * NF + c0), acc);
        if (lane == 0) atomicAdd(&g_cnt[gcur], (float)cnt);
    }
}
__global__ void k_div(float* __restrict__ out) {
    int i = blockIdx.x * blockDim.x + threadIdx.x;
    if (i < NGR * NF)
        out[i] = g_pool[i] / fmaxf(g_cnt[i >> 6], 1.0f);
}

// ---------------- launcher (kernel launches ONLY — no runtime APIs) -------
extern "C" void kernel_launch(void* const* d_in, const int* in_sizes, int n_in,
                              void* d_out, int out_size) {
    const int*   atom_types = (const int*)  d_in[0];
    const float* distances  = (const float*)d_in[1];
    const int*   src        = (const int*)  d_in[2];
    const int*   dst        = (const int*)  d_in[3];
    const int*   gid        = (const int*)  d_in[4];
    const int base = (in_sizes[5] == 1) ? 6 : 5;
    const float* atom_table = (const float*)d_in[base + 0];
    const float* W_embed    = (const float*)d_in[base + 1];
    const float* b_embed    = (const float*)d_in[base + 2];
    const float* W_src      = (const float*)d_in[base + 3];
    const float* b_src      = (const float*)d_in[base + 4];
    const float* W_dst      = (const float*)d_in[base + 5];
    const float* b_dst      = (const float*)d_in[base + 6];
    const float* W_edge     = (const float*)d_in[base + 7];
    const float* b_edge     = (const float*)d_in[base + 8];
    const float* g_msg      = (const float*)d_in[base + 9];
    const float* beta_msg   = (const float*)d_in[base + 10];
    const float* g_bn       = (const float*)d_in[base + 11];
    const float* beta_bn    = (const float*)d_in[base + 12];
    float* out = (float*)d_out;

    k_emb<<<NAT, NF>>>(atom_table, W_embed, b_embed);
    k_gather_x<<<1024, 256>>>(atom_types);               // + zero cursors/edge stats

    k_csr_hist<<<1024, 256>>>(dst);
    k_scan1<<<NCHUNK, 1024>>>();
    k_scan2<<<1, 128>>>();
    k_scan3<<<128, 256>>>();
    k_csr_scatter<<<1024, 256>>>(src, dst, distances);

    k_tab_all<<<(NL * TROWS + 3) / 4, NF2>>>(W_edge, b_edge);

    // layer l: gemm reads x_{l-1} (fused update for l>0), edge passes, stats
    // xsel: l=0 reads g_x; l=1 reads g_x (writes g_x2); l=2 reads g_x2 (writes g_x)
    const int xsel[NL] = { 0, 0, 1 };
    for (int l = 0; l < NL; ++l) {
        k_node_gemm<<<dim3((NN + 127) / 128, 2), 256>>>(
            W_src, b_src, W_dst, b_dst, l, xsel[l], l > 0, g_bn, beta_bn);
        k_edge_stats<<<2048, 256>>>(l);
        k_finalize<<<(l == NL - 1) ? 64 : 1, NF2>>>(g_msg, beta_msg, l, l == NL - 1);
        k_edge_apply<<<2048, 256>>>(l);
    }

    // final update fused into pool: x3 = sp(x2 + BN(h2)); x2 lives in g_x
    k_pool<<<256, 256>>>(gid, g_bn, beta_bn, NL - 1);
    k_div<<<64, 256>>>(out);
}

// round 15
// speedup vs baseline: 1.0111x; 1.0111x over previous
#include <cuda_runtime.h>
#include <cuda_fp16.h>

// ---------------- problem constants (fixed by the dataset) ----------------
#define NN   100000     // nodes
#define NE   1600000    // edges
#define NGR  256        // graphs
#define NF   64         // node feat
#define NF2  128        // 2*NF
#define EFB  40         // rbf bins
#define NL   3          // layers
#define NAT  95         // atom types
#define NAF  200        // atom feat
#define TAB  8192       // e_lin nearest-lookup intervals over [0,8]
#define TROWS (TAB + 1)
#define BN_EPS 1e-5f
#define NCHUNK ((NN + 1023) / 1024)   // 98 scan chunks

// Channel-permuted storage for hs/hd/tab/AB:
//   storage pos p = 8g+r:  r<4 -> orig gate channel 4g+r ; r>=4 -> orig value 64+4g+(r-4)
__device__ __forceinline__ int perm_c(int n) {       // orig -> storage
    return (n < 64) ? (((n >> 2) << 3) | (n & 3))
                    : ((((n & 63) >> 2) << 3) | 4 | (n & 3));
}
__device__ __forceinline__ int orig_c(int p) {       // storage -> orig
    int g = p >> 3, r = p & 7;
    return (r < 4) ? ((g << 2) + r) : (64 + (g << 2) + (r - 4));
}

// ---------------- persistent device scratch (no runtime allocation) -------
__device__ float  g_x   [NN * NF];          // x ping buffer
__device__ float  g_x2  [NN * NF];          // x pong buffer
__device__ __half g_hs  [NN * NF2];         // permuted cols
__device__ __half g_hd  [NN * NF2];         // permuted cols
__device__ float  g_h   [NN * NF];
__device__ __half g_tab [NL * TROWS * NF2]; // all 3 layers, permuted cols
__device__ float  g_emb [NAT * NF];
__device__ int    g_rowptr[NN + 1];
__device__ int    g_cursor[NN];
__device__ int    g_blk [128];
__device__ int    g_csr [NE];               // packed: src | (bin<<17)
__device__ float  g_esum[NF2];
__device__ float  g_esq [NF2];
__device__ float  g_AB  [2 * NF2];
__device__ float  g_nsum[NF];
__device__ float  g_nsq [NF];
__device__ float  g_pool[NGR * NF];
__device__ float  g_cnt [NGR];

// ---------------- helpers -------------------------------------------------
__device__ __forceinline__ float tanh_f(float x) {
    float r; asm("tanh.approx.f32 %0, %1;" : "=f"(r) : "f"(x)); return r;
}
__device__ __forceinline__ float ex2_f(float x) {
    float r; asm("ex2.approx.f32 %0, %1;" : "=f"(r) : "f"(x)); return r;
}
__device__ __forceinline__ float lg2_f(float x) {
    float r; asm("lg2.approx.f32 %0, %1;" : "=f"(r) : "f"(x)); return r;
}
__device__ __forceinline__ float sig_f(float x) {    // 1 MUFU
    return fmaf(0.5f, tanh_f(0.5f * x), 0.5f);
}
__device__ __forceinline__ float sp_f(float x) {     // 2 MUFU, overflow-safe
    float e = ex2_f(-fabsf(x) * 1.4426950408889634f);
    return fmaxf(x, 0.0f) + 0.6931471805599453f * lg2_f(1.0f + e);
}
__device__ __forceinline__ void mma16816(float c[4],
                                         unsigned a0, unsigned a1, unsigned a2, unsigned a3,
                                         unsigned b0, unsigned b1) {
    asm volatile(
        "mma.sync.aligned.m16n8k16.row.col.f32.f16.f16.f32 "
        "{%0,%1,%2,%3}, {%4,%5,%6,%7}, {%8,%9}, {%0,%1,%2,%3};\n"
        : "+f"(c[0]), "+f"(c[1]), "+f"(c[2]), "+f"(c[3])
        : "r"(a0), "r"(a1), "r"(a2), "r"(a3), "r"(b0), "r"(b1));
}

// --------------- 0a: fold atom featurizer + embedding into [95,64] --------
__global__ void k_emb(const float* __restrict__ at, const float* __restrict__ W,
                      const float* __restrict__ b) {
    int a = blockIdx.x, c = threadIdx.x;
    float acc = b[c];
    for (int k = 0; k < NAF; ++k)
        acc += at[a * NAF + k] * W[k * NF + c];
    g_emb[a * NF + c] = acc;
}

// --------------- 0b: x[n] = emb[type[n]]  (+ cursor & edge-stat zeroing) --
__global__ void k_gather_x(const int* __restrict__ types) {
    int i0 = blockIdx.x * blockDim.x + threadIdx.x;
    if (i0 < NF2) { g_esum[i0] = 0.0f; g_esq[i0] = 0.0f; }
    for (int i = i0; i < NN; i += gridDim.x * blockDim.x) g_cursor[i] = 0;
    const int total = NN * (NF / 4);
    for (int i = i0; i < total; i += gridDim.x * blockDim.x) {
        int n = i >> 4, j = i & 15;
        int t = __ldg(&types[n]);
        reinterpret_cast<float4*>(g_x)[i] =
            reinterpret_cast<const float4*>(g_emb)[t * (NF / 4) + j];
    }
}

// --------------- CSR build (one-time) -------------------------------------
__global__ void k_csr_hist(const int* __restrict__ dst) {
    int e = blockIdx.x * blockDim.x + threadIdx.x;
    for (; e < NE; e += gridDim.x * blockDim.x)
        atomicAdd(&g_cursor[__ldg(&dst[e])], 1);
}
__global__ void k_scan1() {
    __shared__ int wsum[32];
    const int tid = threadIdx.x;
    const int i = blockIdx.x * 1024 + tid;
    int v = (i < NN) ? g_cursor[i] : 0;
    int x = v;
#pragma unroll
    for (int off = 1; off < 32; off <<= 1) {
        int y = __shfl_up_sync(0xffffffffu, x, off);
        if ((tid & 31) >= off) x += y;
    }
    if ((tid & 31) == 31) wsum[tid >> 5] = x;
    __syncthreads();
    if (tid < 32) {
        int w = wsum[tid];
#pragma unroll
        for (int off = 1; off < 32; off <<= 1) {
            int y = __shfl_up_sync(0xffffffffu, w, off);
            if (tid >= off) w += y;
        }
        wsum[tid] = w;
    }
    __syncthreads();
    int warpoff = (tid >= 32) ? wsum[(tid >> 5) - 1] : 0;
    int excl = warpoff + x - v;
    if (i < NN) g_rowptr[i] = excl;
    if (tid == 1023) g_blk[blockIdx.x] = warpoff + x;
}
__global__ void k_scan2() {
    __shared__ int s[128];
    const int tid = threadIdx.x;
    int v = (tid < NCHUNK) ? g_blk[tid] : 0;
    s[tid] = v;
    __syncthreads();
    for (int off = 1; off < 128; off <<= 1) {
        int t = (tid >= off) ? s[tid - off] : 0;
        __syncthreads();
        s[tid] += t;
        __syncthreads();
    }
    if (tid < NCHUNK) g_blk[tid] = s[tid] - v;
}
__global__ void k_scan3() {
    int i = blockIdx.x * blockDim.x + threadIdx.x;
    for (; i < NN; i += gridDim.x * blockDim.x) {
        int r = g_rowptr[i] + g_blk[i >> 10];
        g_rowptr[i] = r;
        g_cursor[i] = r;
    }
    if (blockIdx.x == 0 && threadIdx.x == 0) g_rowptr[NN] = NE;
}
__global__ void k_csr_scatter(const int* __restrict__ src, const int* __restrict__ dst,
                              const float* __restrict__ dist) {
    int e = blockIdx.x * blockDim.x + threadIdx.x;
    for (; e < NE; e += gridDim.x * blockDim.x) {
        int d = __ldg(&dst[e]);
        int pos = atomicAdd(&g_cursor[d], 1);
        int bin = min(__float2int_rn(__ldg(&dist[e]) * (TAB / 8.0f)), TAB);
        g_csr[pos] = __ldg(&src[e]) | (bin << 17);
    }
}

// --------------- all-layer e_lin tables (fp16, permuted) ------------------
__global__ void k_tab_all(const float* __restrict__ We, const float* __restrict__ be) {
    __shared__ float phi[4][EFB];
    const int p  = threadIdx.x;
    const int oc = orig_c(p);
    const int r0 = blockIdx.x * 4;
    if (p < EFB) {
        float ctr = p * (8.0f / 39.0f);
#pragma unroll
        for (int r = 0; r < 4; ++r) {
            int grow = r0 + r;
            int rr = grow % TROWS;
            float x = rr * (8.0f / TAB) - ctr;
            phi[r][p] = expf(-4.875f * x * x);
        }
    }
    __syncthreads();
#pragma unroll
    for (int r = 0; r < 4; ++r) {
        int grow = r0 + r;
        if (grow >= NL * TROWS) break;
        int l = grow / TROWS;
        const float* W = We + l * EFB * NF2;
        float acc = be[l * NF2 + oc];
#pragma unroll
        for (int k = 0; k < EFB; ++k)
            acc += phi[r][k] * W[k * NF2 + oc];
        g_tab[grow * NF2 + p] = __float2half_rn(acc);
    }
}

// --------------- node GEMM via tensor cores; optional fused x-update ------
// xsel: 0 -> xin=g_x, xout=g_x2 ; 1 -> xin=g_x2, xout=g_x  (all in-kernel)
__global__ __launch_bounds__(256) void k_node_gemm(
    const float* __restrict__ Wsrc, const float* __restrict__ bsrc,
    const float* __restrict__ Wdst, const float* __restrict__ bdst, int l,
    int xsel, int fuse,
    const float* __restrict__ gb, const float* __restrict__ bb) {
    const float* xin  = xsel ? g_x2 : g_x;
    float*       xout = xsel ? g_x  : g_x2;
    const float* W = (blockIdx.y == 0 ? Wsrc : Wdst) + l * NF * NF2;
    const float* b = (blockIdx.y == 0 ? bsrc : bdst) + l * NF2;
    __half*      H = (blockIdx.y == 0 ? g_hs : g_hd);

    __shared__ __half xs[128 * 72];
    __shared__ __half wt[128 * 72];
    __shared__ float sA[NF], sB[NF];

    const int tid = threadIdx.x;
    const int nb = blockIdx.x * 128;

    if (fuse && tid < NF) {                             // BN consts of layer l-1
        float mean = g_nsum[tid] * (1.0f / NN);
        float var  = fmaxf(g_nsq[tid] * (1.0f / NN) - mean * mean, 0.0f);
        float A = gb[(l - 1) * NF + tid] * rsqrtf(var + BN_EPS);
        sA[tid] = A;
        sB[tid] = bb[(l - 1) * NF + tid] - mean * A;
    }

#pragma unroll
    for (int i = 0; i < 32; ++i) {
        int idx = i * 256 + tid;
        int k = idx >> 7, n = idx & 127;
        wt[n * 72 + k] = __float2half_rn(W[idx]);
    }
    __syncthreads();                                    // sA/sB + wt ready
#pragma unroll
    for (int i = 0; i < 16; ++i) {
        int idx = i * 256 + tid;
        int row = idx >> 5, cp = idx & 31;
        int gr = nb + row;
        int grc = (gr >= NN) ? NN - 1 : gr;
        float2 v = *reinterpret_cast<const float2*>(xin + grc * NF + cp * 2);
        if (fuse) {
            float2 h = *reinterpret_cast<const float2*>(g_h + grc * NF + cp * 2);
            int c0 = cp * 2;
            v.x = sp_f(v.x + sA[c0] * h.x + sB[c0]);
            v.y = sp_f(v.y + sA[c0 + 1] * h.y + sB[c0 + 1]);
            if (blockIdx.y == 0 && gr < NN)
                *reinterpret_cast<float2*>(xout + gr * NF + cp * 2) = v;
        }
        *reinterpret_cast<__half2*>(&xs[row * 72 + cp * 2]) = __floats2half2_rn(v.x, v.y);
    }
    __syncthreads();

    const int w = tid >> 5, lane = tid & 31;
    const int m0 = (w & 3) * 32, n0 = (w >> 2) * 64;
    const int lr = lane >> 2, lc = (lane & 3) * 2;

    float c[2][8][4];
#pragma unroll
    for (int mt = 0; mt < 2; ++mt)
#pragma unroll
        for (int nt = 0; nt < 8; ++nt)
            c[mt][nt][0] = c[mt][nt][1] = c[mt][nt][2] = c[mt][nt][3] = 0.0f;

#pragma unroll
    for (int ks = 0; ks < 4; ++ks) {
        const int kk = ks * 16 + lc;
        unsigned bf[8][2];
#pragma unroll
        for (int nt = 0; nt < 8; ++nt) {
            int n = n0 + nt * 8 + lr;
            bf[nt][0] = *reinterpret_cast<unsigned*>(&wt[n * 72 + kk]);
            bf[nt][1] = *reinterpret_cast<unsigned*>(&wt[n * 72 + kk + 8]);
        }
#pragma unroll
        for (int mt = 0; mt < 2; ++mt) {
            int r = m0 + mt * 16 + lr;
            unsigned a0 = *reinterpret_cast<unsigned*>(&xs[r * 72 + kk]);
            unsigned a1 = *reinterpret_cast<unsigned*>(&xs[(r + 8) * 72 + kk]);
            unsigned a2 = *reinterpret_cast<unsigned*>(&xs[r * 72 + kk + 8]);
            unsigned a3 = *reinterpret_cast<unsigned*>(&xs[(r + 8) * 72 + kk + 8]);
#pragma unroll
            for (int nt = 0; nt < 8; ++nt)
                mma16816(c[mt][nt], a0, a1, a2, a3, bf[nt][0], bf[nt][1]);
        }
    }

#pragma unroll
    for (int nt = 0; nt < 8; ++nt) {
        int n = n0 + nt * 8 + lc;
        int pos = perm_c(n);
        float2 bv = *reinterpret_cast<const float2*>(b + n);
#pragma unroll
        for (int mt = 0; mt < 2; ++mt) {
            int r = nb + m0 + mt * 16 + lr;
            __half2 h01 = __floats2half2_rn(c[mt][nt][0] + bv.x, c[mt][nt][1] + bv.y);
            __half2 h23 = __floats2half2_rn(c[mt][nt][2] + bv.x, c[mt][nt][3] + bv.y);
            if (r < NN)     *reinterpret_cast<__half2*>(H + r * NF2 + pos) = h01;
            if (r + 8 < NN) *reinterpret_cast<__half2*>(H + (r + 8) * NF2 + pos) = h23;
        }
    }
}

// --------------- pass A: CSR stats, 2-edge unrolled (R11-proven) ----------
__global__ __launch_bounds__(256) void k_edge_stats(int l) {
    const int lane = threadIdx.x & 31;
    const int half = lane >> 4;
    const int t    = lane & 15;
    int       wid  = (blockIdx.x * blockDim.x + threadIdx.x) >> 5;
    const int nw   = (gridDim.x * blockDim.x) >> 5;
    const uint4* tabp = reinterpret_cast<const uint4*>(g_tab) + l * TROWS * 16;
    float2 s2[4], q2[4];
#pragma unroll
    for (int j = 0; j < 4; ++j) { s2[j] = make_float2(0, 0); q2[j] = make_float2(0, 0); }

    for (int n = wid; n < NN; n += nw) {
        const int e0 = __ldg(&g_rowptr[n]);
        const int e1 = __ldg(&g_rowptr[n + 1]);
        if (e0 == e1) continue;
        uint4 ub = reinterpret_cast<const uint4*>(g_hd)[n * 16 + t];
        float2 vb[4];
#pragma unroll
        for (int j = 0; j < 4; ++j)
            vb[j] = __half22float2(reinterpret_cast<const __half2*>(&ub)[j]);

        for (int es = e0; es < e1; es += 32) {
            int pk = (es + lane < e1) ? g_csr[es + lane] : 0;
            const int cnt = min(32, e1 - es);
            for (int j = 0; j < cnt; j += 4) {
                int j0 = j + half, j1 = j + 2 + half;
                int pk0 = __shfl_sync(0xffffffffu, pk, j0 & 31);
                int pk1 = __shfl_sync(0xffffffffu, pk, j1 & 31);
                bool a0 = (j0 < cnt), a1 = (j1 < cnt);
                uint4 ua0, ut0, ua1, ut1;
                if (a0) {
                    ua0 = reinterpret_cast<const uint4*>(g_hs)[(pk0 & 0x1FFFF) * 16 + t];
                    ut0 = tabp[(((unsigned)pk0) >> 17) * 16 + t];
                }
                if (a1) {
                    ua1 = reinterpret_cast<const uint4*>(g_hs)[(pk1 & 0x1FFFF) * 16 + t];
                    ut1 = tabp[(((unsigned)pk1) >> 17) * 16 + t];
                }
                if (a0) {
#pragma unroll
                    for (int q = 0; q < 4; ++q) {
                        float2 va = __half22float2(reinterpret_cast<const __half2*>(&ua0)[q]);
                        float2 vt = __half22float2(reinterpret_cast<const __half2*>(&ut0)[q]);
                        float mx = va.x + vb[q].x + vt.x;
                        float my = va.y + vb[q].y + vt.y;
                        s2[q].x += mx;      s2[q].y += my;
                        q2[q].x += mx * mx; q2[q].y += my * my;
                    }
                }
                if (a1) {
#pragma unroll
                    for (int q = 0; q < 4; ++q) {
                        float2 va = __half22float2(reinterpret_cast<const __half2*>(&ua1)[q]);
                        float2 vt = __half22float2(reinterpret_cast<const __half2*>(&ut1)[q]);
                        float mx = va.x + vb[q].x + vt.x;
                        float my = va.y + vb[q].y + vt.y;
                        s2[q].x += mx;      s2[q].y += my;
                        q2[q].x += mx * mx; q2[q].y += my * my;
                    }
                }
            }
        }
    }
    __shared__ float ss[NF2], sq[NF2];
    if (threadIdx.x < NF2) { ss[threadIdx.x] = 0.0f; sq[threadIdx.x] = 0.0f; }
    __syncthreads();
#pragma unroll
    for (int j = 0; j < 4; ++j) {
        atomicAdd(&ss[t * 8 + 2 * j],     s2[j].x);
        atomicAdd(&ss[t * 8 + 2 * j + 1], s2[j].y);
        atomicAdd(&sq[t * 8 + 2 * j],     q2[j].x);
        atomicAdd(&sq[t * 8 + 2 * j + 1], q2[j].y);
    }
    __syncthreads();
    if (threadIdx.x < NF2) {
        atomicAdd(&g_esum[threadIdx.x], ss[threadIdx.x]);
        atomicAdd(&g_esq [threadIdx.x], sq[threadIdx.x]);
    }
}

// --------------- fold BN into y = A*m + B; zero accums for next stage -----
__global__ void k_finalize(const float* __restrict__ gm, const float* __restrict__ bm,
                           int l, int zero_pool) {
    int p = threadIdx.x;                                // 128
    int oc = orig_c(p);
    float mean = g_esum[p] * (1.0f / NE);
    float var  = fmaxf(g_esq[p] * (1.0f / NE) - mean * mean, 0.0f);
    float A = gm[l * NF2 + oc] * rsqrtf(var + BN_EPS);
    g_AB[p]       = A;
    g_AB[NF2 + p] = bm[l * NF2 + oc] - mean * A;
    g_esum[p] = 0.0f;                                   // ready for next layer
    g_esq [p] = 0.0f;
    if (p < NF) { g_nsum[p] = 0.0f; g_nsq[p] = 0.0f; }
    if (zero_pool) {
        for (int i = blockIdx.x * 128 + p; i < NGR * NF + NGR; i += gridDim.x * 128) {
            if (i < NGR * NF) g_pool[i] = 0.0f;
            else g_cnt[i - NGR * NF] = 0.0f;
        }
    }
}

// --------------- pass B: CSR gather, dense gate, 2-edge unrolled ----------
__global__ __launch_bounds__(256) void k_edge_apply(int l) {
    const int lane = threadIdx.x & 31;
    const int half = lane >> 4;
    const int t    = lane & 15;
    int       wid  = (blockIdx.x * blockDim.x + threadIdx.x) >> 5;
    const int nw   = (gridDim.x * blockDim.x) >> 5;
    const uint4* tabp = reinterpret_cast<const uint4*>(g_tab) + l * TROWS * 16;

    const float4 A0 = reinterpret_cast<const float4*>(g_AB)[t * 2];
    const float4 A1 = reinterpret_cast<const float4*>(g_AB)[t * 2 + 1];
    const float4 B0 = reinterpret_cast<const float4*>(g_AB + NF2)[t * 2];
    const float4 B1 = reinterpret_cast<const float4*>(g_AB + NF2)[t * 2 + 1];

    float hsum[4], hsq[4];
#pragma unroll
    for (int i = 0; i < 4; ++i) { hsum[i] = 0.0f; hsq[i] = 0.0f; }

    for (int n = wid; n < NN; n += nw) {
        const int e0 = __ldg(&g_rowptr[n]);
        const int e1 = __ldg(&g_rowptr[n + 1]);

        float hacc[4];
#pragma unroll
        for (int i = 0; i < 4; ++i) hacc[i] = 0.0f;

        if (e0 != e1) {
            uint4 ub = reinterpret_cast<const uint4*>(g_hd)[n * 16 + t];
            float2 vb[4];
#pragma unroll
            for (int j = 0; j < 4; ++j)
                vb[j] = __half22float2(reinterpret_cast<const __half2*>(&ub)[j]);

            for (int es = e0; es < e1; es += 32) {
                int pk = (es + lane < e1) ? g_csr[es + lane] : 0;
                const int cnt = min(32, e1 - es);
                for (int j = 0; j < cnt; j += 4) {
                    int j0 = j + half, j1 = j + 2 + half;
                    int pk0 = __shfl_sync(0xffffffffu, pk, j0 & 31);
                    int pk1 = __shfl_sync(0xffffffffu, pk, j1 & 31);
                    bool a0 = (j0 < cnt), a1 = (j1 < cnt);
                    uint4 ua0, ut0, ua1, ut1;
                    if (a0) {
                        ua0 = reinterpret_cast<const uint4*>(g_hs)[(pk0 & 0x1FFFF) * 16 + t];
                        ut0 = tabp[(((unsigned)pk0) >> 17) * 16 + t];
                    }
                    if (a1) {
                        ua1 = reinterpret_cast<const uint4*>(g_hs)[(pk1 & 0x1FFFF) * 16 + t];
                        ut1 = tabp[(((unsigned)pk1) >> 17) * 16 + t];
                    }
#pragma unroll
                    for (int u = 0; u < 2; ++u) {
                        bool act = u ? a1 : a0;
                        if (!act) continue;
                        const uint4& ua = u ? ua1 : ua0;
                        const uint4& ut = u ? ut1 : ut0;
                        float m[8];
#pragma unroll
                        for (int q = 0; q < 4; ++q) {
                            float2 va = __half22float2(reinterpret_cast<const __half2*>(&ua)[q]);
                            float2 vt = __half22float2(reinterpret_cast<const __half2*>(&ut)[q]);
                            m[2 * q]     = va.x + vb[q].x + vt.x;
                            m[2 * q + 1] = va.y + vb[q].y + vt.y;
                        }
                        float yg0 = A0.x * m[0] + B0.x;
                        float yg1 = A0.y * m[1] + B0.y;
                        float yg2 = A0.z * m[2] + B0.z;
                        float yg3 = A0.w * m[3] + B0.w;
                        float yv0 = A1.x * m[4] + B1.x;
                        float yv1 = A1.y * m[5] + B1.y;
                        float yv2 = A1.z * m[6] + B1.z;
                        float yv3 = A1.w * m[7] + B1.w;
                        hacc[0] += sig_f(yg0) * sp_f(yv0);
                        hacc[1] += sig_f(yg1) * sp_f(yv1);
                        hacc[2] += sig_f(yg2) * sp_f(yv2);
                        hacc[3] += sig_f(yg3) * sp_f(yv3);
                    }
                }
            }
        }
        float tot[4];
#pragma unroll
        for (int i = 0; i < 4; ++i) {
            float o = __shfl_down_sync(0xffffffffu, hacc[i], 16);
            tot[i] = hacc[i] + o;
        }
        if (lane < 16) {
            *reinterpret_cast<float4*>(g_h + n * NF + lane * 4) =
                make_float4(tot[0], tot[1], tot[2], tot[3]);
#pragma unroll
            for (int i = 0; i < 4; ++i) {
                hsum[i] += tot[i];
                hsq[i]  += tot[i] * tot[i];
            }
        }
    }
    __shared__ float ss[NF], sq[NF];
    if (threadIdx.x < NF) { ss[threadIdx.x] = 0.0f; sq[threadIdx.x] = 0.0f; }
    __syncthreads();
    if (lane < 16) {
#pragma unroll
        for (int i = 0; i < 4; ++i) {
            atomicAdd(&ss[t * 4 + i], hsum[i]);
            atomicAdd(&sq[t * 4 + i], hsq[i]);
        }
    }
    __syncthreads();
    if (threadIdx.x < NF) {
        atomicAdd(&g_nsum[threadIdx.x], ss[threadIdx.x]);
        atomicAdd(&g_nsq [threadIdx.x], sq[threadIdx.x]);
    }
}

// --------------- pool: fused final x-update + segmented sum (gid sorted) --
__global__ __launch_bounds__(256) void k_pool(const int* __restrict__ gid,
                                              const float* __restrict__ gb,
                                              const float* __restrict__ bb, int l) {
    __shared__ float sA[NF], sB[NF];
    const int tid = threadIdx.x;
    if (tid < NF) {
        float mean = g_nsum[tid] * (1.0f / NN);
        float var  = fmaxf(g_nsq[tid] * (1.0f / NN) - mean * mean, 0.0f);
        float A = gb[l * NF + tid] * rsqrtf(var + BN_EPS);
        sA[tid] = A;
        sB[tid] = bb[l * NF + tid] - mean * A;
    }
    __syncthreads();

    const int lane = tid & 31;
    const int wid  = (blockIdx.x * blockDim.x + tid) >> 5;
    const int nwarp = (gridDim.x * blockDim.x) >> 5;
    const int per = (NN + nwarp - 1) / nwarp;
    const int n0 = wid * per;
    const int n1 = min(NN, n0 + per);
    if (n0 >= n1) return;

    const int c0 = (lane & 15) * 4;
    float4 acc = make_float4(0, 0, 0, 0);
    int cnt = 0, gcur = -1;

    for (int n = n0; n < n1; ++n) {
        int g = __ldg(&gid[n]);
        if (g != gcur) {
            if (cnt > 0 && lane < 16) {
                atomicAdd(reinterpret_cast<float4*>(g_pool + gcur * NF + c0), acc);
                if (lane == 0) atomicAdd(&g_cnt[gcur], (float)cnt);
            }
            acc = make_float4(0, 0, 0, 0);
            cnt = 0;
            gcur = g;
        }
        if (lane < 16) {
            float4 xv = *reinterpret_cast<const float4*>(g_x + n * NF + c0);
            float4 hv = *reinterpret_cast<const float4*>(g_h + n * NF + c0);
            acc.x += sp_f(xv.x + sA[c0]     * hv.x + sB[c0]);
            acc.y += sp_f(xv.y + sA[c0 + 1] * hv.y + sB[c0 + 1]);
            acc.z += sp_f(xv.z + sA[c0 + 2] * hv.z + sB[c0 + 2]);
            acc.w += sp_f(xv.w + sA[c0 + 3] * hv.w + sB[c0 + 3]);
        }
        ++cnt;
    }
    if (cnt > 0 && lane < 16) {
        atomicAdd(reinterpret_cast<float4*>(g_pool + gcur * NF + c0), acc);
        if (lane == 0) atomicAdd(&g_cnt[gcur], (float)cnt);
    }
}
__global__ void k_div(float* __restrict__ out) {
    int i = blockIdx.x * blockDim.x + threadIdx.x;
    if (i < NGR * NF)
        out[i] = g_pool[i] / fmaxf(g_cnt[i >> 6], 1.0f);
}

// ---------------- launcher (kernel launches ONLY — no runtime APIs) -------
extern "C" void kernel_launch(void* const* d_in, const int* in_sizes, int n_in,
                              void* d_out, int out_size) {
    const int*   atom_types = (const int*)  d_in[0];
    const float* distances  = (const float*)d_in[1];
    const int*   src        = (const int*)  d_in[2];
    const int*   dst        = (const int*)  d_in[3];
    const int*   gid        = (const int*)  d_in[4];
    const int base = (in_sizes[5] == 1) ? 6 : 5;
    const float* atom_table = (const float*)d_in[base + 0];
    const float* W_embed    = (const float*)d_in[base + 1];
    const float* b_embed    = (const float*)d_in[base + 2];
    const float* W_src      = (const float*)d_in[base + 3];
    const float* b_src      = (const float*)d_in[base + 4];
    const float* W_dst      = (const float*)d_in[base + 5];
    const float* b_dst      = (const float*)d_in[base + 6];
    const float* W_edge     = (const float*)d_in[base + 7];
    const float* b_edge     = (const float*)d_in[base + 8];
    const float* g_msg      = (const float*)d_in[base + 9];
    const float* beta_msg   = (const float*)d_in[base + 10];
    const float* g_bn       = (const float*)d_in[base + 11];
    const float* beta_bn    = (const float*)d_in[base + 12];
    float* out = (float*)d_out;

    k_emb<<<NAT, NF>>>(atom_table, W_embed, b_embed);
    k_gather_x<<<1024, 256>>>(atom_types);               // + zero cursors/edge stats

    k_csr_hist<<<1024, 256>>>(dst);
    k_scan1<<<NCHUNK, 1024>>>();
    k_scan2<<<1, 128>>>();
    k_scan3<<<128, 256>>>();
    k_csr_scatter<<<1024, 256>>>(src, dst, distances);

    k_tab_all<<<(NL * TROWS + 3) / 4, NF2>>>(W_edge, b_edge);

    // xsel: l=0 reads g_x; l=1 reads g_x (writes g_x2); l=2 reads g_x2 (writes g_x)
    const int xsel[NL] = { 0, 0, 1 };
    for (int l = 0; l < NL; ++l) {
        k_node_gemm<<<dim3((NN + 127) / 128, 2), 256>>>(
            W_src, b_src, W_dst, b_dst, l, xsel[l], l > 0, g_bn, beta_bn);
        k_edge_stats<<<2048, 256>>>(l);
        k_finalize<<<(l == NL - 1) ? 64 : 1, NF2>>>(g_msg, beta_msg, l, l == NL - 1);
        k_edge_apply<<<2048, 256>>>(l);
    }

    // final update fused into pool: x3 = sp(x2 + BN(h2)); x2 lives in g_x
    k_pool<<<256, 256>>>(gid, g_bn, beta_bn, NL - 1);
    k_div<<<64, 256>>>(out);
}